// round 6
// baseline (speedup 1.0000x reference)
#include <cuda_runtime.h>
#include <math_constants.h>

#define K_LEN 1024
#define I_LEN 8192
#define DIM   128

#define NSTRIP 8                 // DP CTAs (one SM each), 1024 cols per strip
#define TPB    128               // DP threads per CTA
#define NW     4                 // warps per DP CTA
#define CPT    8                 // columns per thread
// p_local(t) = t + 2*(t>>5)  in [0,133];  SPAN = 134
#define SPAN   134
#define GAP    16                // inter-CTA skew slack (steps)
#define BASEP(b) ((b) * (SPAN + GAP))
#define LSTEPS 1158              // local steps (0..1156 valid), mult of 3
#define SROWS_L 1161             // rows per strip (prefetch margin)
#define STRIDE (SROWS_L * 1024)
#define CANARY 0x7FC00001u       // NaN payload; valid D is never NaN

// Scratch (alloc-free rule: __device__ globals)
// Per-strip locally-skewed cost: strip b, row (m + p_local), col l
__device__ float g_S[NSTRIP * STRIDE];                 // ~38 MB
__device__ float g_k2[K_LEN];
__device__ float g_x2[I_LEN];
// boundary slots: g_bnd[b][r] = D[r][ (b+1)*1024 - 1 ], packed (val<<32)|(r+1)
__device__ unsigned long long g_bnd[NSTRIP][K_LEN];

__device__ __forceinline__ unsigned long long ld_rlx(const unsigned long long* p) {
    unsigned long long v;
    asm volatile("ld.relaxed.gpu.global.b64 %0, [%1];" : "=l"(v) : "l"(p));
    return v;
}
__device__ __forceinline__ void st_rlx(unsigned long long* p, unsigned long long v) {
    asm volatile("st.relaxed.gpu.global.b64 [%0], %1;" :: "l"(p), "l"(v));
}

// ---------------------------------------------------------------------------
// Kernel 1: row norms + zero boundary slots + INF triangles + zero extra outs.
// ---------------------------------------------------------------------------
__global__ void norms_kernel(const float* __restrict__ kern,
                             const float* __restrict__ x,
                             float* __restrict__ out, int out_size) {
    int gtid = blockIdx.x * blockDim.x + threadIdx.x;
    if (gtid < out_size) out[gtid] = 0.0f;
    if (gtid < NSTRIP * K_LEN) ((unsigned long long*)g_bnd)[gtid] = 0ull;

    // INF triangle per strip: rows srow < p_local(thread owning the col group)
    if (gtid < NSTRIP * SPAN * 256) {
        int strip = gtid / (SPAN * 256);
        int rem   = gtid % (SPAN * 256);
        int srow  = rem / 256;
        int grp   = rem % 256;              // float4 group; cols grp*4..grp*4+3
        int t     = grp >> 1;               // owning thread (8 cols/thread)
        int pl    = t + 2 * (t >> 5);
        if (srow < pl) {
            float4 inf4 = make_float4(CUDART_INF_F, CUDART_INF_F,
                                      CUDART_INF_F, CUDART_INF_F);
            *(float4*)(g_S + (size_t)strip * STRIDE + srow * 1024 + grp * 4) = inf4;
        }
    }

    int warp = gtid >> 5;
    int lane = threadIdx.x & 31;
    if (warp >= K_LEN + I_LEN) return;
    const float* row = (warp < K_LEN) ? (kern + warp * DIM)
                                      : (x + (warp - K_LEN) * DIM);
    float4 v = ((const float4*)row)[lane];
    float s = v.x * v.x + v.y * v.y + v.z * v.z + v.w * v.w;
#pragma unroll
    for (int off = 16; off; off >>= 1) s += __shfl_xor_sync(0xffffffffu, s, off);
    if (lane == 0) {
        if (warp < K_LEN) g_k2[warp] = s;
        else              g_x2[warp - K_LEN] = s;
    }
}

// ---------------------------------------------------------------------------
// Kernel 2: cost GEMM, epilogue writes per-strip locally-skewed layout.
// ---------------------------------------------------------------------------
#define BM 64
#define BN 64
#define BK 64

__global__ __launch_bounds__(256) void cost_gemm(const float* __restrict__ A,
                                                 const float* __restrict__ B) {
    __shared__ float As[BK][BM + 4];
    __shared__ float Bs[BK][BN + 4];
    const int tx = threadIdx.x & 15;
    const int ty = threadIdx.x >> 4;
    const int m0 = blockIdx.y * BM;
    const int n0 = blockIdx.x * BN;
    const int t  = threadIdx.x;

    float acc[4][4] = {};

    for (int k0 = 0; k0 < DIM; k0 += BK) {
#pragma unroll
        for (int i = 0; i < 4; i++) {
            int idx = t + i * 256;
            int row = idx >> 4;
            int c4  = idx & 15;
            float4 va = *(const float4*)(A + (size_t)(m0 + row) * DIM + k0 + c4 * 4);
            As[c4 * 4 + 0][row] = va.x;
            As[c4 * 4 + 1][row] = va.y;
            As[c4 * 4 + 2][row] = va.z;
            As[c4 * 4 + 3][row] = va.w;
            float4 vb = *(const float4*)(B + (size_t)(n0 + row) * DIM + k0 + c4 * 4);
            Bs[c4 * 4 + 0][row] = vb.x;
            Bs[c4 * 4 + 1][row] = vb.y;
            Bs[c4 * 4 + 2][row] = vb.z;
            Bs[c4 * 4 + 3][row] = vb.w;
        }
        __syncthreads();
#pragma unroll 16
        for (int kk = 0; kk < BK; kk++) {
            float a[4], b[4];
            *(float4*)a = *(const float4*)&As[kk][ty * 4];
            *(float4*)b = *(const float4*)&Bs[kk][tx * 4];
#pragma unroll
            for (int i = 0; i < 4; i++)
#pragma unroll
                for (int j = 0; j < 4; j++)
                    acc[i][j] += a[i] * b[j];
        }
        __syncthreads();
    }

    const int n  = n0 + tx * 4;        // 4 cols, stays inside one 8-col group
    const int bs = n >> 10;            // strip
    const int l  = n & 1023;           // local col
    const int th = l >> 3;             // owning DP thread
    const int pl = th + 2 * (th >> 5); // its local position skew
#pragma unroll
    for (int i = 0; i < 4; i++) {
        int m = m0 + ty * 4 + i;
        float k2 = g_k2[m];
        float4 outv;
        float* ov = (float*)&outv;
#pragma unroll
        for (int j = 0; j < 4; j++) {
            float cv = k2 + g_x2[n + j] - 2.0f * acc[i][j];
            ov[j] = fmaxf(cv, 0.0f);
        }
        *(float4*)(g_S + (size_t)bs * STRIDE + (m + pl) * 1024 + l) = outv;
    }
}

// ---------------------------------------------------------------------------
// Kernel 3: multi-CTA register-systolic DTW. CTA b owns cols [1024b,1024b+1024).
// Thread t at local position p = t + 2*warp; at local step sl computes row
// r = sl - p of its 8 columns. Left dep: shfl_up (intra-warp), smem slot from
// step sl-3 (cross-warp), L2 slot g_bnd[b-1][r] (cross-CTA, 17 steps of skew
// slack, depth-3 prefetched, poll fallback). Diag = previous step's left.
// ---------------------------------------------------------------------------
__global__ __launch_bounds__(TPB, 1) void dtw_systolic(float* __restrict__ out) {
    __shared__ volatile unsigned int slots[NW - 1][LSTEPS];   // ~14 KB
    const float INF = CUDART_INF_F;
    const int tid  = threadIdx.x;
    const int lane = tid & 31;
    const int w    = tid >> 5;
    const int b    = blockIdx.x;
    const int p    = tid + 2 * w;            // local position, 0..133
    const float* Sb = g_S + (size_t)b * STRIDE;
    const float* cp = Sb + (size_t)tid * CPT;

    for (int i = tid; i < (NW - 1) * LSTEPS; i += TPB)
        ((volatile unsigned int*)slots)[i] = CANARY;
    __syncthreads();

    float Dp[CPT];
#pragma unroll
    for (int j = 0; j < CPT; j++) Dp[j] = INF;
    float bprev = (b == 0 && tid == 0) ? 0.0f : INF;
    float lastD = INF;

    // cost ring (use at sl, loaded at sl-2)
    float4 B0[2], B1[2], B2[2];
    {
        const float4* p0 = (const float4*)(cp);
        const float4* p1 = (const float4*)(cp + 1024);
        B0[0] = p0[0]; B0[1] = p0[1];
        B1[0] = p1[0]; B1[1] = p1[1];
    }
    // boundary ring for rows sl, sl+1, sl+2 (lane 0 of warp 0, b>0 only)
    unsigned long long nb0 = 0, nb1 = 0, nb2 = 0;
    if (tid == 0 && b > 0) {
        nb0 = ld_rlx(&g_bnd[b - 1][0]);
        nb1 = ld_rlx(&g_bnd[b - 1][1]);
        nb2 = ld_rlx(&g_bnd[b - 1][2]);
    }

#define STEP(SL, CUR, PF, NBU, NBP)                                            \
    {                                                                          \
        const int sl = (SL);                                                   \
        /* cost prefetch row sl+2 (disjoint regs) */                           \
        {                                                                      \
            const float4* np = (const float4*)(cp + (size_t)(sl + 2) * 1024);  \
            PF[0] = np[0]; PF[1] = np[1];                                      \
        }                                                                      \
        float shf = __shfl_up_sync(0xffffffffu, lastD, 1);                     \
        float b_in;                                                            \
        if (lane == 0) {                                                       \
            int r = sl - p;                                                    \
            if (w > 0) {                                                       \
                if (r >= 0 && r < K_LEN) {                                     \
                    unsigned v = slots[w - 1][sl - 3];                         \
                    while (v == CANARY) v = slots[w - 1][sl - 3];              \
                    b_in = __uint_as_float(v);                                 \
                } else b_in = INF;                                             \
            } else if (b > 0 && r < K_LEN) {      /* r == sl >= 0 */           \
                unsigned long long v = NBU;                                    \
                if ((unsigned)v != (unsigned)(r + 1)) {                        \
                    do { v = ld_rlx(&g_bnd[b - 1][r]); }                       \
                    while ((unsigned)v != (unsigned)(r + 1));                  \
                }                                                              \
                b_in = __uint_as_float((unsigned)(v >> 32));                   \
            } else b_in = INF;                                                 \
            /* boundary prefetch for row sl+3 */                               \
            if (w == 0 && b > 0 && sl + 3 < K_LEN)                             \
                NBP = ld_rlx(&g_bnd[b - 1][sl + 3]);                           \
        } else b_in = shf;                                                     \
        const float* cc = (const float*)CUR;                                   \
        float run = fminf(fminf(b_in, bprev), Dp[0]) + cc[0];                  \
        float prevOld = Dp[0];                                                 \
        Dp[0] = run;                                                           \
        _Pragma("unroll")                                                      \
        for (int j = 1; j < CPT; j++) {                                        \
            float tt = fminf(prevOld, Dp[j]);                                  \
            prevOld = Dp[j];                                                   \
            run = fminf(run, tt) + cc[j];                                      \
            Dp[j] = run;                                                       \
        }                                                                      \
        bprev = b_in;                                                          \
        lastD = run;                                                           \
        if (lane == 31 && w < NW - 1)                                          \
            slots[w][sl] = __float_as_uint(run);                               \
        if (tid == TPB - 1) {                                                  \
            int rp = sl - (SPAN - 1);                                          \
            if (b < NSTRIP - 1 && rp >= 0 && rp < K_LEN)                       \
                st_rlx(&g_bnd[b][rp],                                          \
                       ((unsigned long long)__float_as_uint(run) << 32)        \
                           | (unsigned)(rp + 1));                              \
            if (b == NSTRIP - 1 && sl == SPAN - 1 + K_LEN - 1) out[0] = run;   \
        }                                                                      \
    }

    for (int ss = 0; ss < LSTEPS; ss += 3) {
        STEP(ss + 0, B0, B2, nb0, nb0)
        STEP(ss + 1, B1, B0, nb1, nb1)
        STEP(ss + 2, B2, B1, nb2, nb2)
    }
#undef STEP
}

// ---------------------------------------------------------------------------
extern "C" void kernel_launch(void* const* d_in, const int* in_sizes, int n_in,
                              void* d_out, int out_size) {
    const float* kern = (const float*)d_in[0];
    const float* x    = (const float*)d_in[1];
    if (n_in >= 2 && in_sizes[0] == I_LEN * DIM && in_sizes[1] == K_LEN * DIM) {
        kern = (const float*)d_in[1];
        x    = (const float*)d_in[0];
    }

    int nwarp_rows = K_LEN + I_LEN;
    norms_kernel<<<(nwarp_rows + 7) / 8, 256>>>(kern, x, (float*)d_out, out_size);

    dim3 grid(I_LEN / BN, K_LEN / BM);
    cost_gemm<<<grid, 256>>>(kern, x);

    dtw_systolic<<<NSTRIP, TPB>>>((float*)d_out);
}

// round 7
// speedup vs baseline: 1.4084x; 1.4084x over previous
#include <cuda_runtime.h>
#include <math_constants.h>

#define K_LEN 1024
#define I_LEN 8192
#define DIM   128

// Scratch (alloc-free rule: __device__ globals)
__device__ float g_C[K_LEN * I_LEN];   // 32 MB cost matrix
__device__ float g_k2[K_LEN];
__device__ float g_x2[I_LEN];

// ---------------------------------------------------------------------------
// Kernel 1: squared row norms for both inputs. One warp per row.
// ---------------------------------------------------------------------------
__global__ void norms_kernel(const float* __restrict__ kern,
                             const float* __restrict__ x) {
    int warp = (blockIdx.x * blockDim.x + threadIdx.x) >> 5;
    int lane = threadIdx.x & 31;
    if (warp >= K_LEN + I_LEN) return;
    const float* row = (warp < K_LEN) ? (kern + warp * DIM)
                                      : (x + (warp - K_LEN) * DIM);
    float4 v = ((const float4*)row)[lane];          // 32 lanes * 4 = 128
    float s = v.x * v.x + v.y * v.y + v.z * v.z + v.w * v.w;
#pragma unroll
    for (int off = 16; off; off >>= 1) s += __shfl_xor_sync(0xffffffffu, s, off);
    if (lane == 0) {
        if (warp < K_LEN) g_k2[warp] = s;
        else              g_x2[warp - K_LEN] = s;
    }
}

// ---------------------------------------------------------------------------
// Kernel 2: C[m][n] = max(k2[m] + x2[n] - 2 * <kern_m, x_n>, 0)
// 128x128 tile, BK=8, 256 threads, 8x8 microtile, double-buffered smem.
// __launch_bounds__(256, 2): ~128 regs available -> NO spills (the R1-R6
// version was register-capped and spilled its accumulators).
// ---------------------------------------------------------------------------
#define BM 128
#define BN 128
#define BK 8

__global__ __launch_bounds__(256, 2) void cost_gemm(const float* __restrict__ A,
                                                    const float* __restrict__ B) {
    __shared__ float As[2][BK][BM + 4];
    __shared__ float Bs[2][BK][BN + 4];
    const int tid = threadIdx.x;
    const int m0 = blockIdx.y * BM;
    const int n0 = blockIdx.x * BN;
    const int lr = tid >> 1;           // loader row 0..127
    const int lc = (tid & 1) * 4;      // loader col 0 or 4
    const int tx = tid & 15;           // micro-tile col group
    const int ty = tid >> 4;           // micro-tile row group

    float acc[8][8];
#pragma unroll
    for (int i = 0; i < 8; i++)
#pragma unroll
        for (int j = 0; j < 8; j++) acc[i][j] = 0.0f;

    // preload k0 = 0 into buffer 0
    {
        float4 va = *(const float4*)(A + (size_t)(m0 + lr) * DIM + lc);
        float4 vb = *(const float4*)(B + (size_t)(n0 + lr) * DIM + lc);
        As[0][lc + 0][lr] = va.x; As[0][lc + 1][lr] = va.y;
        As[0][lc + 2][lr] = va.z; As[0][lc + 3][lr] = va.w;
        Bs[0][lc + 0][lr] = vb.x; Bs[0][lc + 1][lr] = vb.y;
        Bs[0][lc + 2][lr] = vb.z; Bs[0][lc + 3][lr] = vb.w;
    }
    __syncthreads();

    int buf = 0;
    for (int k0 = 0; k0 < DIM; k0 += BK) {
        const bool has_next = (k0 + BK < DIM);
        float4 na, nb;
        if (has_next) {
            na = *(const float4*)(A + (size_t)(m0 + lr) * DIM + k0 + BK + lc);
            nb = *(const float4*)(B + (size_t)(n0 + lr) * DIM + k0 + BK + lc);
        }
#pragma unroll
        for (int k = 0; k < BK; k++) {
            float a[8], b[8];
            *(float4*)(a)     = *(const float4*)&As[buf][k][ty * 8];
            *(float4*)(a + 4) = *(const float4*)&As[buf][k][ty * 8 + 4];
            *(float4*)(b)     = *(const float4*)&Bs[buf][k][tx * 8];
            *(float4*)(b + 4) = *(const float4*)&Bs[buf][k][tx * 8 + 4];
#pragma unroll
            for (int i = 0; i < 8; i++)
#pragma unroll
                for (int j = 0; j < 8; j++)
                    acc[i][j] += a[i] * b[j];
        }
        if (has_next) {
            const int nbuf = buf ^ 1;
            As[nbuf][lc + 0][lr] = na.x; As[nbuf][lc + 1][lr] = na.y;
            As[nbuf][lc + 2][lr] = na.z; As[nbuf][lc + 3][lr] = na.w;
            Bs[nbuf][lc + 0][lr] = nb.x; Bs[nbuf][lc + 1][lr] = nb.y;
            Bs[nbuf][lc + 2][lr] = nb.z; Bs[nbuf][lc + 3][lr] = nb.w;
            __syncthreads();
            buf = nbuf;
        }
    }

    // epilogue: c = max(k2 + x2 - 2*dot, 0), row-major into g_C
    float x2v[8];
#pragma unroll
    for (int j = 0; j < 8; j++) x2v[j] = g_x2[n0 + tx * 8 + j];
#pragma unroll
    for (int i = 0; i < 8; i++) {
        const int m = m0 + ty * 8 + i;
        const float k2 = g_k2[m];
        float4 o0, o1;
        o0.x = fmaxf(k2 + x2v[0] - 2.0f * acc[i][0], 0.0f);
        o0.y = fmaxf(k2 + x2v[1] - 2.0f * acc[i][1], 0.0f);
        o0.z = fmaxf(k2 + x2v[2] - 2.0f * acc[i][2], 0.0f);
        o0.w = fmaxf(k2 + x2v[3] - 2.0f * acc[i][3], 0.0f);
        o1.x = fmaxf(k2 + x2v[4] - 2.0f * acc[i][4], 0.0f);
        o1.y = fmaxf(k2 + x2v[5] - 2.0f * acc[i][5], 0.0f);
        o1.z = fmaxf(k2 + x2v[6] - 2.0f * acc[i][6], 0.0f);
        o1.w = fmaxf(k2 + x2v[7] - 2.0f * acc[i][7], 0.0f);
        float* dst = g_C + (size_t)m * I_LEN + n0 + tx * 8;
        *(float4*)(dst)     = o0;
        *(float4*)(dst + 4) = o1;
    }
}

// ---------------------------------------------------------------------------
// Kernel 3: DTW DP via (min,+) scan. Single CTA, 1024 threads, 8 cols/thread.
// (byte-identical to the Round-1 version — best measured DP)
// ---------------------------------------------------------------------------
__global__ __launch_bounds__(1024, 1) void dtw_dp(float* __restrict__ out,
                                                  int out_size) {
    __shared__ float sh_bound[1024];
    __shared__ float shC[32];
    __shared__ float shE[32];
    const float INF = CUDART_INF_F;
    const int tid  = threadIdx.x;
    const int lane = tid & 31;
    const int wid  = tid >> 5;

    for (int i = tid; i < out_size; i += 1024)
        if (i > 0) out[i] = 0.0f;

    float Dp[8];
#pragma unroll
    for (int j = 0; j < 8; j++) Dp[j] = INF;
    sh_bound[tid] = INF;

    float c[8];
    {
        const float* crow = g_C + tid * 8;
        float4 v0 = *(const float4*)(crow);
        float4 v1 = *(const float4*)(crow + 4);
        c[0] = v0.x; c[1] = v0.y; c[2] = v0.z; c[3] = v0.w;
        c[4] = v1.x; c[5] = v1.y; c[6] = v1.z; c[7] = v1.w;
    }
    __syncthreads();

    for (int r = 0; r < K_LEN; r++) {
        float dleft = (tid == 0) ? ((r == 0) ? 0.0f : INF) : sh_bound[tid - 1];
        float e[8];
        e[0] = fminf(dleft, Dp[0]) + c[0];
#pragma unroll
        for (int j = 1; j < 8; j++) e[j] = fminf(Dp[j - 1], Dp[j]) + c[j];

        float4 n0 = make_float4(0.f, 0.f, 0.f, 0.f);
        float4 n1 = n0;
        if (r + 1 < K_LEN) {
            const float* nrow = g_C + (size_t)(r + 1) * I_LEN + tid * 8;
            n0 = *(const float4*)(nrow);
            n1 = *(const float4*)(nrow + 4);
        }

        float Cl = c[0], El = e[0];
#pragma unroll
        for (int j = 1; j < 8; j++) {
            El = fminf(El + c[j], e[j]);
            Cl += c[j];
        }

#pragma unroll
        for (int off = 1; off < 32; off <<= 1) {
            float Cu = __shfl_up_sync(0xffffffffu, Cl, off);
            float Eu = __shfl_up_sync(0xffffffffu, El, off);
            if (lane >= off) {
                El = fminf(Eu + Cl, El);
                Cl = Cu + Cl;
            }
        }
        if (lane == 31) { shC[wid] = Cl; shE[wid] = El; }
        __syncthreads();

        float Cp = shC[lane];
        float Ep = shE[lane];
#pragma unroll
        for (int off = 1; off < 32; off <<= 1) {
            float Cu = __shfl_up_sync(0xffffffffu, Cp, off);
            float Eu = __shfl_up_sync(0xffffffffu, Ep, off);
            if (lane >= off) {
                Ep = fminf(Eu + Cp, Ep);
                Cp = Cu + Cp;
            }
        }
        float wC = __shfl_sync(0xffffffffu, Cp, (wid - 1) & 31);
        float wE = __shfl_sync(0xffffffffu, Ep, (wid - 1) & 31);
        if (wid == 0) { wC = 0.0f; wE = INF; }

        float exC = __shfl_up_sync(0xffffffffu, Cl, 1);
        float exE = __shfl_up_sync(0xffffffffu, El, 1);
        if (lane == 0) { exC = 0.0f; exE = INF; }

        float D = fminf(wE + exC, exE);

#pragma unroll
        for (int j = 0; j < 8; j++) {
            D = fminf(D + c[j], e[j]);
            Dp[j] = D;
        }
        sh_bound[tid] = Dp[7];

        c[0] = n0.x; c[1] = n0.y; c[2] = n0.z; c[3] = n0.w;
        c[4] = n1.x; c[5] = n1.y; c[6] = n1.z; c[7] = n1.w;
        __syncthreads();
    }

    if (tid == 1023) out[0] = Dp[7];
}

// ---------------------------------------------------------------------------
extern "C" void kernel_launch(void* const* d_in, const int* in_sizes, int n_in,
                              void* d_out, int out_size) {
    const float* kern = (const float*)d_in[0];
    const float* x    = (const float*)d_in[1];
    if (n_in >= 2 && in_sizes[0] == I_LEN * DIM && in_sizes[1] == K_LEN * DIM) {
        kern = (const float*)d_in[1];
        x    = (const float*)d_in[0];
    }

    int nwarp_rows = K_LEN + I_LEN;
    norms_kernel<<<(nwarp_rows + 7) / 8, 256>>>(kern, x);

    dim3 grid(I_LEN / BN, K_LEN / BM);
    cost_gemm<<<grid, 256>>>(kern, x);

    dtw_dp<<<1, 1024>>>((float*)d_out, out_size);
}